// round 1
// baseline (speedup 1.0000x reference)
#include <cuda_runtime.h>
#include <cuda_bf16.h>
#include <mma.h>
#include <cstdint>
#include <cstddef>

using namespace nvcuda;

#define B_    4
#define T_    256
#define U_    64
#define DENC  512
#define DDEC  512
#define INF_  1024
#define V_    1024
#define NROW  (B_*T_*U_)   /* 65536 */

// ---------------- scratch (__device__ globals: no allocation allowed) -------
__device__ __nv_bfloat16 g_encB[B_*T_*DENC];
__device__ __nv_bfloat16 g_decB[B_*U_*DDEC];
__device__ __nv_bfloat16 g_WencB[DENC*INF_];
__device__ __nv_bfloat16 g_WdecB[DDEC*INF_];
__device__ __nv_bfloat16 g_WfcB[INF_*V_];
__device__ float         g_pe[B_*T_*INF_];
__device__ float         g_pd[B_*U_*INF_];
__device__ __nv_bfloat16 g_A[(size_t)NROW*INF_];   // 128 MB: tanh(pe+pd+bias) in bf16

static __device__ __forceinline__ float tanh_fast(float x) {
    float y; asm("tanh.approx.f32 %0, %1;" : "=f"(y) : "f"(x)); return y;
}

// ---------------- fp32 -> bf16 convert (vectorized) -------------------------
__global__ void f2bf4_kernel(const float* __restrict__ in,
                             __nv_bfloat16* __restrict__ out, int n4) {
    int stride = gridDim.x * blockDim.x;
    for (int i = blockIdx.x * blockDim.x + threadIdx.x; i < n4; i += stride) {
        float4 v = reinterpret_cast<const float4*>(in)[i];
        __nv_bfloat162 lo = __floats2bfloat162_rn(v.x, v.y);
        __nv_bfloat162 hi = __floats2bfloat162_rn(v.z, v.w);
        reinterpret_cast<__nv_bfloat162*>(out)[2*(size_t)i + 0] = lo;
        reinterpret_cast<__nv_bfloat162*>(out)[2*(size_t)i + 1] = hi;
    }
}

// ---------------- bf16 wmma GEMM: C[M,N] = A[M,K] @ B[K,N]  (fp32 accum) ----
#define BM  128
#define BN  128
#define BKk 32
#define LDA 40     // 32 + 8 pad (bf16 elems)
#define LDB 136    // 128 + 8 pad

__global__ __launch_bounds__(256)
void gemm_bf16_kernel(const __nv_bfloat16* __restrict__ A,
                      const __nv_bfloat16* __restrict__ Bm,
                      float* __restrict__ C,
                      int M, int N, int K,
                      const int* __restrict__ tmask_lens /* null = no skip */) {
    __shared__ __nv_bfloat16 sA[BM][LDA];
    __shared__ __nv_bfloat16 sB[BKk][LDB];

    const int bm = blockIdx.y, bn = blockIdx.x;

    // Masked-tile skip (logits GEMM only): 128 rows = 2 consecutive t values,
    // whole tile is masked iff the first t is already >= enc_len[b].
    if (tmask_lens) {
        int r0 = bm * BM;
        int bb = r0 >> 14;            // / (T*U)
        int t0 = (r0 >> 6) & 255;     // / U  % T
        if (t0 >= tmask_lens[bb]) return;
    }

    const int tid    = threadIdx.x;
    const int wid    = tid >> 5;
    const int warp_m = wid & 1;   // 2 warps over M  -> 64-row warp tile
    const int warp_n = wid >> 1;  // 4 warps over N  -> 32-col warp tile

    wmma::fragment<wmma::accumulator,16,16,16,float> acc[4][2];
    #pragma unroll
    for (int i = 0; i < 4; i++)
        #pragma unroll
        for (int j = 0; j < 2; j++) wmma::fill_fragment(acc[i][j], 0.0f);

    const int arow = tid >> 1;            // 128 rows, 2 threads/row
    const int aseg = (tid & 1) * 16;      // 16 bf16 each
    const int brow = tid >> 3;            // 32 rows, 8 threads/row
    const int bcol = (tid & 7) * 16;      // 16 bf16 each

    const size_t Abase = (size_t)bm * BM * K;
    const size_t Bn0   = (size_t)bn * BN;

    for (int k0 = 0; k0 < K; k0 += BKk) {
        // global loads into registers first (overlaps previous tile's MMAs)
        const uint4* ga = reinterpret_cast<const uint4*>(A + Abase + (size_t)arow*K + k0 + aseg);
        uint4 a0 = ga[0], a1 = ga[1];
        const uint4* gb = reinterpret_cast<const uint4*>(Bm + (size_t)(k0 + brow)*N + Bn0 + bcol);
        uint4 b0 = gb[0], b1 = gb[1];

        __syncthreads();   // previous tile fully consumed
        *reinterpret_cast<uint4*>(&sA[arow][aseg    ]) = a0;
        *reinterpret_cast<uint4*>(&sA[arow][aseg + 8]) = a1;
        *reinterpret_cast<uint4*>(&sB[brow][bcol    ]) = b0;
        *reinterpret_cast<uint4*>(&sB[brow][bcol + 8]) = b1;
        __syncthreads();

        #pragma unroll
        for (int kk = 0; kk < BKk; kk += 16) {
            wmma::fragment<wmma::matrix_a,16,16,16,__nv_bfloat16,wmma::row_major> fa[4];
            wmma::fragment<wmma::matrix_b,16,16,16,__nv_bfloat16,wmma::row_major> fb[2];
            #pragma unroll
            for (int i = 0; i < 4; i++)
                wmma::load_matrix_sync(fa[i], &sA[warp_m*64 + i*16][kk], LDA);
            #pragma unroll
            for (int j = 0; j < 2; j++)
                wmma::load_matrix_sync(fb[j], &sB[kk][warp_n*32 + j*16], LDB);
            #pragma unroll
            for (int i = 0; i < 4; i++)
                #pragma unroll
                for (int j = 0; j < 2; j++)
                    wmma::mma_sync(acc[i][j], fa[i], fb[j], acc[i][j]);
        }
    }

    #pragma unroll
    for (int i = 0; i < 4; i++)
        #pragma unroll
        for (int j = 0; j < 2; j++) {
            size_t row = (size_t)bm*BM + warp_m*64 + i*16;
            size_t col = Bn0 + warp_n*32 + j*16;
            wmma::store_matrix_sync(C + row*N + col, acc[i][j], N, wmma::mem_row_major);
        }
}

// ---------------- A = bf16( tanh(pe + pd + b_enc + b_dec) ) ------------------
__global__ void build_A_kernel(const float* __restrict__ b_enc,
                               const float* __restrict__ b_dec) {
    const int total4 = NROW * (INF_/4);   // 16.7M float4 groups
    const int stride = gridDim.x * blockDim.x;
    for (int i = blockIdx.x*blockDim.x + threadIdx.x; i < total4; i += stride) {
        int r  = i >> 8;          // row (1024/4 = 256 groups per row)
        int fq = i & 255;
        int b = r >> 14, t = (r >> 6) & 255, u = r & 63;
        float4 pe = reinterpret_cast<const float4*>(g_pe)[(b*T_ + t)*(INF_/4) + fq];
        float4 pd = reinterpret_cast<const float4*>(g_pd)[(b*U_ + u)*(INF_/4) + fq];
        float4 be = reinterpret_cast<const float4*>(b_enc)[fq];
        float4 bd = reinterpret_cast<const float4*>(b_dec)[fq];
        float x0 = tanh_fast(pe.x + pd.x + be.x + bd.x);
        float x1 = tanh_fast(pe.y + pd.y + be.y + bd.y);
        float x2 = tanh_fast(pe.z + pd.z + be.z + bd.z);
        float x3 = tanh_fast(pe.w + pd.w + be.w + bd.w);
        __nv_bfloat162 lo = __floats2bfloat162_rn(x0, x1);
        __nv_bfloat162 hi = __floats2bfloat162_rn(x2, x3);
        reinterpret_cast<__nv_bfloat162*>(g_A)[2*(size_t)i + 0] = lo;
        reinterpret_cast<__nv_bfloat162*>(g_A)[2*(size_t)i + 1] = hi;
    }
}

// ---------------- per-row log-softmax (+bias, +mask), in place ---------------
__global__ __launch_bounds__(128)
void softmax_mask_kernel(float* __restrict__ out, const float* __restrict__ b_fc,
                         const int* __restrict__ enc_lens,
                         const int* __restrict__ dec_lens) {
    const int r = blockIdx.x;
    const int b = r >> 14, t = (r >> 6) & 255, u = r & 63;
    float4* row = reinterpret_cast<float4*>(out + (size_t)r * V_);
    const int tid = threadIdx.x;

    if (t >= enc_lens[b] || u >= dec_lens[b]) {
        float4 z = make_float4(0.f, 0.f, 0.f, 0.f);
        row[tid] = z; row[tid + 128] = z;
        return;
    }

    const float4* bias = reinterpret_cast<const float4*>(b_fc);
    float4 v0 = row[tid],     b0 = bias[tid];
    float4 v1 = row[tid+128], b1 = bias[tid+128];
    v0.x += b0.x; v0.y += b0.y; v0.z += b0.z; v0.w += b0.w;
    v1.x += b1.x; v1.y += b1.y; v1.z += b1.z; v1.w += b1.w;

    float mx = fmaxf(fmaxf(fmaxf(v0.x,v0.y), fmaxf(v0.z,v0.w)),
                     fmaxf(fmaxf(v1.x,v1.y), fmaxf(v1.z,v1.w)));
    #pragma unroll
    for (int o = 16; o > 0; o >>= 1) mx = fmaxf(mx, __shfl_xor_sync(0xffffffffu, mx, o));
    __shared__ float sred[4];
    const int wid = tid >> 5, lane = tid & 31;
    if (lane == 0) sred[wid] = mx;
    __syncthreads();
    mx = fmaxf(fmaxf(sred[0], sred[1]), fmaxf(sred[2], sred[3]));

    float s = __expf(v0.x-mx)+__expf(v0.y-mx)+__expf(v0.z-mx)+__expf(v0.w-mx)
            + __expf(v1.x-mx)+__expf(v1.y-mx)+__expf(v1.z-mx)+__expf(v1.w-mx);
    #pragma unroll
    for (int o = 16; o > 0; o >>= 1) s += __shfl_xor_sync(0xffffffffu, s, o);
    __shared__ float ssum[4];
    if (lane == 0) ssum[wid] = s;
    __syncthreads();
    s = ssum[0] + ssum[1] + ssum[2] + ssum[3];

    const float lse = mx + __logf(s);
    v0.x -= lse; v0.y -= lse; v0.z -= lse; v0.w -= lse;
    v1.x -= lse; v1.y -= lse; v1.z -= lse; v1.w -= lse;
    row[tid] = v0; row[tid + 128] = v1;
}

// ---------------- launch ----------------------------------------------------
extern "C" void kernel_launch(void* const* d_in, const int* in_sizes, int n_in,
                              void* d_out, int out_size) {
    const float* enc      = (const float*)d_in[0];
    const float* dec      = (const float*)d_in[1];
    const float* W_enc    = (const float*)d_in[2];
    const float* b_enc    = (const float*)d_in[3];
    const float* W_dec    = (const float*)d_in[4];
    const float* b_dec    = (const float*)d_in[5];
    const float* W_fc     = (const float*)d_in[6];
    const float* b_fc     = (const float*)d_in[7];
    const int*   enc_lens = (const int*)d_in[8];
    const int*   dec_lens = (const int*)d_in[9];
    float*       out      = (float*)d_out;
    (void)in_sizes; (void)n_in; (void)out_size;

    void *p_encB, *p_decB, *p_WencB, *p_WdecB, *p_WfcB, *p_pe, *p_pd, *p_A;
    cudaGetSymbolAddress(&p_encB,  g_encB);
    cudaGetSymbolAddress(&p_decB,  g_decB);
    cudaGetSymbolAddress(&p_WencB, g_WencB);
    cudaGetSymbolAddress(&p_WdecB, g_WdecB);
    cudaGetSymbolAddress(&p_WfcB,  g_WfcB);
    cudaGetSymbolAddress(&p_pe,    g_pe);
    cudaGetSymbolAddress(&p_pd,    g_pd);
    cudaGetSymbolAddress(&p_A,     g_A);

    auto cvt = [](const float* src, void* dst, int n) {
        int n4 = n / 4;
        int blocks = (n4 + 255) / 256; if (blocks > 2048) blocks = 2048;
        f2bf4_kernel<<<blocks, 256>>>(src, (__nv_bfloat16*)dst, n4);
    };
    cvt(enc,   p_encB,  B_*T_*DENC);
    cvt(dec,   p_decB,  B_*U_*DDEC);
    cvt(W_enc, p_WencB, DENC*INF_);
    cvt(W_dec, p_WdecB, DDEC*INF_);
    cvt(W_fc,  p_WfcB,  INF_*V_);

    // pe = enc @ W_enc   [1024 x 1024, K=512]
    gemm_bf16_kernel<<<dim3(INF_/BN, (B_*T_)/BM), 256>>>(
        (const __nv_bfloat16*)p_encB, (const __nv_bfloat16*)p_WencB,
        (float*)p_pe, B_*T_, INF_, DENC, nullptr);
    // pd = dec @ W_dec   [256 x 1024, K=512]
    gemm_bf16_kernel<<<dim3(INF_/BN, (B_*U_)/BM), 256>>>(
        (const __nv_bfloat16*)p_decB, (const __nv_bfloat16*)p_WdecB,
        (float*)p_pd, B_*U_, INF_, DDEC, nullptr);

    // A = tanh(pe + pd + biases) in bf16
    build_A_kernel<<<1024, 256>>>(b_enc, b_dec);

    // logits = A @ W_fc  -> d_out (scratch), masked t-tiles skipped
    gemm_bf16_kernel<<<dim3(V_/BN, NROW/BM), 256>>>(
        (const __nv_bfloat16*)p_A, (const __nv_bfloat16*)p_WfcB,
        out, NROW, V_, INF_, enc_lens);

    // log-softmax + bias + mask, in place
    softmax_mask_kernel<<<NROW, 128>>>(out, b_fc, enc_lens, dec_lens);
}

// round 3
// speedup vs baseline: 1.1158x; 1.1158x over previous
#include <cuda_runtime.h>
#include <cuda_bf16.h>
#include <mma.h>
#include <cstdint>
#include <cstddef>

using namespace nvcuda;

#define B_    4
#define T_    256
#define U_    64
#define DENC  512
#define DDEC  512
#define INF_  1024
#define V_    1024
#define NROW  (B_*T_*U_)   /* 65536 */

// ---------------- scratch (__device__ globals: no allocation allowed) -------
__device__ __nv_bfloat16 g_encB[B_*T_*DENC];
__device__ __nv_bfloat16 g_decB[B_*U_*DDEC];
__device__ __nv_bfloat16 g_WencB[DENC*INF_];
__device__ __nv_bfloat16 g_WdecB[DDEC*INF_];
__device__ __nv_bfloat16 g_WfcB[INF_*V_];          // W_fc bf16, [K][V] row-major
__device__ float         g_pe[B_*T_*INF_];          // pe' = enc@W_enc + b_enc + b_dec
__device__ float         g_pd[B_*U_*INF_];          // pd  = dec@W_dec

// ======================= helpers ============================================
static __device__ __forceinline__ uint32_t smem_u32(const void* p) {
    uint32_t a;
    asm("{ .reg .u64 t; cvta.to.shared.u64 t, %1; cvt.u32.u64 %0, t; }" : "=r"(a) : "l"(p));
    return a;
}
static __device__ __forceinline__ void cp_async16(uint32_t dst, const void* src) {
    asm volatile("cp.async.cg.shared.global [%0], [%1], 16;" :: "r"(dst), "l"(src));
}
static __device__ __forceinline__ void cp_commit() {
    asm volatile("cp.async.commit_group;" ::: "memory");
}
template<int N> static __device__ __forceinline__ void cp_wait() {
    asm volatile("cp.async.wait_group %0;" :: "n"(N) : "memory");
}
static __device__ __forceinline__ uint32_t tanh2_bf16(uint32_t h2) {
    uint32_t r; asm("tanh.approx.bf16x2 %0, %1;" : "=r"(r) : "r"(h2)); return r;
}

// =================== fused big GEMM: logits = tanh(pe'+pd) @ W_fc ============
// CTA tile 128(M) x 256(N), K-chunk 32, 32 chunks. A generated on the fly.
#define NC      32
#define SA_PITCH 40          /* bf16 elems, 32 + 8 pad */
#define SB_PITCH 264         /* bf16 elems, 256 + 8 pad */
#define PD_PITCH 36          /* fp32 elems, 32 + 4 pad */
// dynamic smem layout (bytes):
#define OFF_SA  0                                  /* 2 *128*40*2  = 20480 */
#define OFF_SB  20480                              /* 3 * 32*264*2 = 50688 */
#define OFF_PD  71168                              /* 3 * 64*36*4  = 27648 */
#define OFF_PE  98816                              /* 3 *  2*32*4  =   768 */
#define SMEM_TOTAL_BYTES 99584

__global__ __launch_bounds__(256, 1)
void joint_gemm_kernel(const float* __restrict__ pe,
                       const float* __restrict__ pd,
                       const __nv_bfloat16* __restrict__ Bw,   /* [K][V] bf16 */
                       float* __restrict__ C,
                       const int* __restrict__ enc_lens) {
    extern __shared__ char sm[];
    __nv_bfloat16* sA = (__nv_bfloat16*)(sm + OFF_SA);
    __nv_bfloat16* sB = (__nv_bfloat16*)(sm + OFF_SB);
    float*         sPD = (float*)(sm + OFF_PD);
    float*         sPE = (float*)(sm + OFF_PE);

    const int bn = blockIdx.x;            // 4 N-tiles of 256
    const int bm = blockIdx.y;            // 512 M-tiles of 128
    const int r0 = bm << 7;
    const int b  = r0 >> 14;
    const int t0 = (r0 >> 6) & 255;
    if (t0 >= enc_lens[b]) return;        // fully-masked tile: softmax zero-fills

    const int tid = threadIdx.x;
    const int wid = tid >> 5;
    const int warp_m = wid & 1;           // 2 warps over M (64 rows)
    const int warp_n = wid >> 1;          // 4 warps over N (64 cols)

    const float* peRow = pe + (size_t)(b*T_ + t0) * INF_;     // 2 rows
    const float* pdRow = pd + (size_t)(b*U_) * INF_;          // 64 rows
    const __nv_bfloat16* Bg = Bw + (size_t)(bn << 8);

    const uint32_t sB_u  = smem_u32(sB);
    const uint32_t sPD_u = smem_u32(sPD);
    const uint32_t sPE_u = smem_u32(sPE);

    // -------- producer: cp.async one K-chunk of B (32x256), pd (64x32), pe (2x32)
    auto issue = [&](int c) {
        const int s = c % 3;
        const int k0 = c << 5;
        {   // B: 1024 x 16B segs, 4 per thread
            const uint32_t d0 = sB_u + (uint32_t)s * (32*SB_PITCH*2);
            #pragma unroll
            for (int i = 0; i < 4; i++) {
                int seg = tid + (i << 8);
                int row = seg >> 5, cs = seg & 31;
                cp_async16(d0 + row*(SB_PITCH*2) + (cs << 4),
                           Bg + (size_t)(k0 + row) * V_ + (cs << 3));
            }
        }
        {   // pd: 512 x 16B segs, 2 per thread
            const uint32_t d0 = sPD_u + (uint32_t)s * (64*PD_PITCH*4);
            #pragma unroll
            for (int i = 0; i < 2; i++) {
                int seg = tid + (i << 8);
                int row = seg >> 3, cs = seg & 7;
                cp_async16(d0 + row*(PD_PITCH*4) + (cs << 4),
                           pdRow + (size_t)row * INF_ + k0 + (cs << 2));
            }
        }
        if (tid < 16) {   // pe: 2 rows x 128B
            const uint32_t d0 = sPE_u + (uint32_t)s * 256;
            int row = tid >> 3, cs = tid & 7;
            cp_async16(d0 + row*128 + (cs << 4),
                       peRow + (size_t)row * INF_ + k0 + (cs << 2));
        }
        cp_commit();
    };

    // -------- A-gen: tanh(pe'+pd) -> bf16 -> sA stage (16 elems/thread)
    auto genA = [&](int c) {
        const int s  = c % 3;
        const int st = c & 1;
        const int row  = tid >> 1;
        const int kseg = (tid & 1) << 4;
        const int u = row & 63, tt = row >> 6;
        const float4* pd4 = (const float4*)(sPD + s*(64*PD_PITCH) + u*PD_PITCH + kseg);
        const float4* pe4 = (const float4*)(sPE + s*64 + tt*32 + kseg);
        uint32_t outv[8];
        #pragma unroll
        for (int i = 0; i < 4; i++) {
            float4 a = pd4[i], e = pe4[i];
            __nv_bfloat162 h0 = __floats2bfloat162_rn(a.x + e.x, a.y + e.y);
            __nv_bfloat162 h1 = __floats2bfloat162_rn(a.z + e.z, a.w + e.w);
            outv[2*i]   = tanh2_bf16(*(uint32_t*)&h0);
            outv[2*i+1] = tanh2_bf16(*(uint32_t*)&h1);
        }
        __nv_bfloat16* dst = sA + st*(128*SA_PITCH) + row*SA_PITCH + kseg;
        *(uint4*)(dst)     = make_uint4(outv[0], outv[1], outv[2], outv[3]);
        *(uint4*)(dst + 8) = make_uint4(outv[4], outv[5], outv[6], outv[7]);
    };

    wmma::fragment<wmma::accumulator,16,16,16,float> acc[4][4];
    #pragma unroll
    for (int i = 0; i < 4; i++)
        #pragma unroll
        for (int j = 0; j < 4; j++) wmma::fill_fragment(acc[i][j], 0.0f);

    issue(0); issue(1); issue(2);
    cp_wait<2>();
    __syncthreads();
    genA(0);

    for (int c = 0; c < NC; c++) {
        __syncthreads();   // sA[c&1] + B chunk c visible to all

        const __nv_bfloat16* aS = sA + (c & 1)*(128*SA_PITCH) + warp_m*64*SA_PITCH;
        const __nv_bfloat16* bS = sB + (c % 3)*(32*SB_PITCH) + warp_n*64;
        #pragma unroll
        for (int kk = 0; kk < 32; kk += 16) {
            wmma::fragment<wmma::matrix_a,16,16,16,__nv_bfloat16,wmma::row_major> fa[4];
            wmma::fragment<wmma::matrix_b,16,16,16,__nv_bfloat16,wmma::row_major> fb[4];
            #pragma unroll
            for (int i = 0; i < 4; i++)
                wmma::load_matrix_sync(fa[i], aS + i*16*SA_PITCH + kk, SA_PITCH);
            #pragma unroll
            for (int j = 0; j < 4; j++)
                wmma::load_matrix_sync(fb[j], bS + kk*SB_PITCH + j*16, SB_PITCH);
            #pragma unroll
            for (int i = 0; i < 4; i++)
                #pragma unroll
                for (int j = 0; j < 4; j++)
                    wmma::mma_sync(acc[i][j], fa[i], fb[j], acc[i][j]);
        }

        __syncthreads();   // chunk-c stage fully consumed

        if (c + 3 < NC) issue(c + 3);
        if (c + 1 < NC) {
            if (c + 3 < NC)      cp_wait<2>();
            else if (c + 2 < NC) cp_wait<1>();
            else                 cp_wait<0>();
            __syncthreads();     // chunk c+1 cp.async data visible to all
            genA(c + 1);
        }
    }

    // -------- epilogue: store 128x256 fp32 tile
    #pragma unroll
    for (int i = 0; i < 4; i++)
        #pragma unroll
        for (int j = 0; j < 4; j++) {
            size_t row = (size_t)r0 + warp_m*64 + i*16;
            size_t col = (size_t)(bn << 8) + warp_n*64 + j*16;
            wmma::store_matrix_sync(C + row*V_ + col, acc[i][j], V_, wmma::mem_row_major);
        }
}

// ---------------- fp32 -> bf16 convert (vectorized) -------------------------
__global__ void f2bf4_kernel(const float* __restrict__ in,
                             __nv_bfloat16* __restrict__ out, int n4) {
    int stride = gridDim.x * blockDim.x;
    for (int i = blockIdx.x * blockDim.x + threadIdx.x; i < n4; i += stride) {
        float4 v = reinterpret_cast<const float4*>(in)[i];
        __nv_bfloat162 lo = __floats2bfloat162_rn(v.x, v.y);
        __nv_bfloat162 hi = __floats2bfloat162_rn(v.z, v.w);
        reinterpret_cast<__nv_bfloat162*>(out)[2*(size_t)i + 0] = lo;
        reinterpret_cast<__nv_bfloat162*>(out)[2*(size_t)i + 1] = hi;
    }
}

// ---------------- pe' = pe + b_enc + b_dec (elementwise) ---------------------
__global__ void biasadd_pe_kernel(float* __restrict__ pe,
                                  const float* __restrict__ be,
                                  const float* __restrict__ bd) {
    int i = blockIdx.x * blockDim.x + threadIdx.x;    // float4 index
    int kq = i & 255;                                 // 256 float4 per row
    float4 v = reinterpret_cast<float4*>(pe)[i];
    float4 a = reinterpret_cast<const float4*>(be)[kq];
    float4 c = reinterpret_cast<const float4*>(bd)[kq];
    v.x += a.x + c.x; v.y += a.y + c.y; v.z += a.z + c.z; v.w += a.w + c.w;
    reinterpret_cast<float4*>(pe)[i] = v;
}

// ---------------- bf16 wmma GEMM (small projections) -------------------------
#define BM  128
#define BN  128
#define BKk 32
#define LDA 40
#define LDB 136

__global__ __launch_bounds__(256)
void gemm_bf16_kernel(const __nv_bfloat16* __restrict__ A,
                      const __nv_bfloat16* __restrict__ Bm,
                      float* __restrict__ C,
                      int M, int N, int K) {
    __shared__ __nv_bfloat16 sA[BM][LDA];
    __shared__ __nv_bfloat16 sB[BKk][LDB];

    const int bm = blockIdx.y, bn = blockIdx.x;
    const int tid    = threadIdx.x;
    const int wid    = tid >> 5;
    const int warp_m = wid & 1;
    const int warp_n = wid >> 1;

    wmma::fragment<wmma::accumulator,16,16,16,float> acc[4][2];
    #pragma unroll
    for (int i = 0; i < 4; i++)
        #pragma unroll
        for (int j = 0; j < 2; j++) wmma::fill_fragment(acc[i][j], 0.0f);

    const int arow = tid >> 1;
    const int aseg = (tid & 1) * 16;
    const int brow = tid >> 3;
    const int bcol = (tid & 7) * 16;

    const size_t Abase = (size_t)bm * BM * K;
    const size_t Bn0   = (size_t)bn * BN;

    for (int k0 = 0; k0 < K; k0 += BKk) {
        const uint4* ga = reinterpret_cast<const uint4*>(A + Abase + (size_t)arow*K + k0 + aseg);
        uint4 a0 = ga[0], a1 = ga[1];
        const uint4* gb = reinterpret_cast<const uint4*>(Bm + (size_t)(k0 + brow)*N + Bn0 + bcol);
        uint4 b0 = gb[0], b1 = gb[1];

        __syncthreads();
        *reinterpret_cast<uint4*>(&sA[arow][aseg    ]) = a0;
        *reinterpret_cast<uint4*>(&sA[arow][aseg + 8]) = a1;
        *reinterpret_cast<uint4*>(&sB[brow][bcol    ]) = b0;
        *reinterpret_cast<uint4*>(&sB[brow][bcol + 8]) = b1;
        __syncthreads();

        #pragma unroll
        for (int kk = 0; kk < BKk; kk += 16) {
            wmma::fragment<wmma::matrix_a,16,16,16,__nv_bfloat16,wmma::row_major> fa[4];
            wmma::fragment<wmma::matrix_b,16,16,16,__nv_bfloat16,wmma::row_major> fb[2];
            #pragma unroll
            for (int i = 0; i < 4; i++)
                wmma::load_matrix_sync(fa[i], &sA[warp_m*64 + i*16][kk], LDA);
            #pragma unroll
            for (int j = 0; j < 2; j++)
                wmma::load_matrix_sync(fb[j], &sB[kk][warp_n*32 + j*16], LDB);
            #pragma unroll
            for (int i = 0; i < 4; i++)
                #pragma unroll
                for (int j = 0; j < 2; j++)
                    wmma::mma_sync(acc[i][j], fa[i], fb[j], acc[i][j]);
        }
    }

    #pragma unroll
    for (int i = 0; i < 4; i++)
        #pragma unroll
        for (int j = 0; j < 2; j++) {
            size_t row = (size_t)bm*BM + warp_m*64 + i*16;
            size_t col = Bn0 + warp_n*32 + j*16;
            wmma::store_matrix_sync(C + row*N + col, acc[i][j], N, wmma::mem_row_major);
        }
}

// ---------------- per-row log-softmax (+bias, +mask), in place ---------------
__global__ __launch_bounds__(128)
void softmax_mask_kernel(float* __restrict__ out, const float* __restrict__ b_fc,
                         const int* __restrict__ enc_lens,
                         const int* __restrict__ dec_lens) {
    const int r = blockIdx.x;
    const int b = r >> 14, t = (r >> 6) & 255, u = r & 63;
    float4* row = reinterpret_cast<float4*>(out + (size_t)r * V_);
    const int tid = threadIdx.x;

    if (t >= enc_lens[b] || u >= dec_lens[b]) {
        float4 z = make_float4(0.f, 0.f, 0.f, 0.f);
        row[tid] = z; row[tid + 128] = z;
        return;
    }

    const float4* bias = reinterpret_cast<const float4*>(b_fc);
    float4 v0 = row[tid],     b0 = bias[tid];
    float4 v1 = row[tid+128], b1 = bias[tid+128];
    v0.x += b0.x; v0.y += b0.y; v0.z += b0.z; v0.w += b0.w;
    v1.x += b1.x; v1.y += b1.y; v1.z += b1.z; v1.w += b1.w;

    float mx = fmaxf(fmaxf(fmaxf(v0.x,v0.y), fmaxf(v0.z,v0.w)),
                     fmaxf(fmaxf(v1.x,v1.y), fmaxf(v1.z,v1.w)));
    #pragma unroll
    for (int o = 16; o > 0; o >>= 1) mx = fmaxf(mx, __shfl_xor_sync(0xffffffffu, mx, o));
    __shared__ float sred[4];
    const int wid = tid >> 5, lane = tid & 31;
    if (lane == 0) sred[wid] = mx;
    __syncthreads();
    mx = fmaxf(fmaxf(sred[0], sred[1]), fmaxf(sred[2], sred[3]));

    float s = __expf(v0.x-mx)+__expf(v0.y-mx)+__expf(v0.z-mx)+__expf(v0.w-mx)
            + __expf(v1.x-mx)+__expf(v1.y-mx)+__expf(v1.z-mx)+__expf(v1.w-mx);
    #pragma unroll
    for (int o = 16; o > 0; o >>= 1) s += __shfl_xor_sync(0xffffffffu, s, o);
    __shared__ float ssum[4];
    if (lane == 0) ssum[wid] = s;
    __syncthreads();
    s = ssum[0] + ssum[1] + ssum[2] + ssum[3];

    const float lse = mx + __logf(s);
    v0.x -= lse; v0.y -= lse; v0.z -= lse; v0.w -= lse;
    v1.x -= lse; v1.y -= lse; v1.z -= lse; v1.w -= lse;
    row[tid] = v0; row[tid + 128] = v1;
}

// ---------------- launch ----------------------------------------------------
extern "C" void kernel_launch(void* const* d_in, const int* in_sizes, int n_in,
                              void* d_out, int out_size) {
    const float* enc      = (const float*)d_in[0];
    const float* dec      = (const float*)d_in[1];
    const float* W_enc    = (const float*)d_in[2];
    const float* b_enc    = (const float*)d_in[3];
    const float* W_dec    = (const float*)d_in[4];
    const float* b_dec    = (const float*)d_in[5];
    const float* W_fc     = (const float*)d_in[6];
    const float* b_fc     = (const float*)d_in[7];
    const int*   enc_lens = (const int*)d_in[8];
    const int*   dec_lens = (const int*)d_in[9];
    float*       out      = (float*)d_out;
    (void)in_sizes; (void)n_in; (void)out_size;

    void *p_encB, *p_decB, *p_WencB, *p_WdecB, *p_WfcB, *p_pe, *p_pd;
    cudaGetSymbolAddress(&p_encB,  g_encB);
    cudaGetSymbolAddress(&p_decB,  g_decB);
    cudaGetSymbolAddress(&p_WencB, g_WencB);
    cudaGetSymbolAddress(&p_WdecB, g_WdecB);
    cudaGetSymbolAddress(&p_WfcB,  g_WfcB);
    cudaGetSymbolAddress(&p_pe,    g_pe);
    cudaGetSymbolAddress(&p_pd,    g_pd);

    auto cvt = [](const float* src, void* dst, int n) {
        int n4 = n / 4;
        int blocks = (n4 + 255) / 256; if (blocks > 2048) blocks = 2048;
        f2bf4_kernel<<<blocks, 256>>>(src, (__nv_bfloat16*)dst, n4);
    };
    cvt(enc,   p_encB,  B_*T_*DENC);
    cvt(dec,   p_decB,  B_*U_*DDEC);
    cvt(W_enc, p_WencB, DENC*INF_);
    cvt(W_dec, p_WdecB, DDEC*INF_);
    cvt(W_fc,  p_WfcB,  INF_*V_);

    // pe = enc @ W_enc, pd = dec @ W_dec
    gemm_bf16_kernel<<<dim3(INF_/BN, (B_*T_)/BM), 256>>>(
        (const __nv_bfloat16*)p_encB, (const __nv_bfloat16*)p_WencB,
        (float*)p_pe, B_*T_, INF_, DENC);
    gemm_bf16_kernel<<<dim3(INF_/BN, (B_*U_)/BM), 256>>>(
        (const __nv_bfloat16*)p_decB, (const __nv_bfloat16*)p_WdecB,
        (float*)p_pd, B_*U_, INF_, DDEC);

    // pe' = pe + b_enc + b_dec
    biasadd_pe_kernel<<<(B_*T_*INF_/4 + 255)/256, 256>>>((float*)p_pe, b_enc, b_dec);

    // logits = tanh(pe'+pd) @ W_fc  (A generated on the fly), masked tiles skipped
    cudaFuncSetAttribute(joint_gemm_kernel,
                         cudaFuncAttributeMaxDynamicSharedMemorySize, SMEM_TOTAL_BYTES);
    joint_gemm_kernel<<<dim3(V_/256, NROW/128), 256, SMEM_TOTAL_BYTES>>>(
        (const float*)p_pe, (const float*)p_pd,
        (const __nv_bfloat16*)p_WfcB, out, enc_lens);

    // log-softmax + bias + mask, in place
    softmax_mask_kernel<<<NROW, 128>>>(out, b_fc, enc_lens, dec_lens);
}